// round 1
// baseline (speedup 1.0000x reference)
#include <cuda_runtime.h>

// LinearAttentionTriton: out = (per-trunk Q K^T V) @ (V^T K)
// Restructured as: S = V^T K (global 64x64, fp32, deterministic 2-stage reduce)
//                  out_t = Q_t @ (K_t^T @ (V_t @ S))
//
// N = 262144, D = 64, TRUNK = 128, T = 2048.

#define D 64
#define TRUNK 128
#define NBLK1 512          // blocks for partial V^T K reduction

// scratch (no cudaMalloc allowed) — device globals
__device__ __align__(16) float g_S[D * D];
__device__ __align__(16) float g_part[NBLK1 * D * D];

// ---------------- f32x2 helpers (Blackwell packed fp32 FMA) ----------------

__device__ __forceinline__ unsigned long long bcast2(float x) {
    unsigned long long r;
    asm("mov.b64 %0, {%1, %1};" : "=l"(r) : "f"(x));
    return r;
}

__device__ __forceinline__ void f2(unsigned long long& d,
                                   unsigned long long a,
                                   unsigned long long b) {
    // d = a * b + d, elementwise on two packed fp32 lanes
    asm("fma.rn.f32x2 %0, %1, %2, %0;" : "+l"(d) : "l"(a), "l"(b));
}

// ---------------- Kernel 1: partial S = V^T K over a row slab ----------------
// grid = NBLK1, block = 256. Each block reduces N/NBLK1 rows in fixed order.
__global__ void __launch_bounds__(256) k_partialS(const float* __restrict__ Kg,
                                                  const float* __restrict__ Vg,
                                                  int N) {
    __shared__ float sK[64 * 64];
    __shared__ float sV[64 * 64];

    const int tid = threadIdx.x;
    const int blk = blockIdx.x;
    const int rpb = N / NBLK1;       // rows per block (512 for N=262144)
    const int chunks = rpb >> 6;     // 64-row chunks

    const int d0 = (tid >> 3) * 2;   // 32 groups * 2 = 64 d-rows
    const int e0 = (tid & 7) * 8;    // 8 groups * 8 = 64 e-cols

    unsigned long long acc[2][4];
#pragma unroll
    for (int i = 0; i < 2; ++i)
#pragma unroll
        for (int j = 0; j < 4; ++j) acc[i][j] = 0ull;

    const float4* K4 = (const float4*)Kg;
    const float4* V4 = (const float4*)Vg;
    const long base4 = (long)blk * rpb * 16;   // float4 units (row*64/4)

    for (int c = 0; c < chunks; ++c) {
        const long cb = base4 + (long)c * 1024;
        for (int i = tid; i < 1024; i += 256) {
            ((float4*)sK)[i] = K4[cb + i];
            ((float4*)sV)[i] = V4[cb + i];
        }
        __syncthreads();

#pragma unroll 4
        for (int r = 0; r < 64; ++r) {
            const float a0 = sV[r * 64 + d0];
            const float a1 = sV[r * 64 + d0 + 1];
            const unsigned long long pa0 = bcast2(a0);
            const unsigned long long pa1 = bcast2(a1);
            const ulonglong2 b01 = *(const ulonglong2*)&sK[r * 64 + e0];
            const ulonglong2 b23 = *(const ulonglong2*)&sK[r * 64 + e0 + 4];
            f2(acc[0][0], pa0, b01.x); f2(acc[0][1], pa0, b01.y);
            f2(acc[0][2], pa0, b23.x); f2(acc[0][3], pa0, b23.y);
            f2(acc[1][0], pa1, b01.x); f2(acc[1][1], pa1, b01.y);
            f2(acc[1][2], pa1, b23.x); f2(acc[1][3], pa1, b23.y);
        }
        __syncthreads();
    }

    float* dst = &g_part[blk * 4096];
#pragma unroll
    for (int i = 0; i < 2; ++i) {
        *(ulonglong2*)&dst[(d0 + i) * 64 + e0]     = make_ulonglong2(acc[i][0], acc[i][1]);
        *(ulonglong2*)&dst[(d0 + i) * 64 + e0 + 4] = make_ulonglong2(acc[i][2], acc[i][3]);
    }
}

// ---------------- Kernel 2: reduce partials -> g_S (deterministic) ----------------
__global__ void __launch_bounds__(256) k_reduceS() {
    const int e = blockIdx.x * 256 + threadIdx.x;   // 16 blocks * 256 = 4096
    float acc = 0.0f;
#pragma unroll 8
    for (int p = 0; p < NBLK1; ++p) acc += g_part[p * 4096 + e];
    g_S[e] = acc;
}

// ---------------- Kernel 3: per-trunk out_t = Q_t (K_t^T (V_t S)) ----------------
// grid = T, block = 512, dynamic smem 116736 B.
// smem layout (floats): sS[4096] | sA[128*68] | sK[128*64] | sT1[128*64]
// sT2 aliases sS (S is dead after GEMM1).
#define SA_STRIDE 68   // pad to kill bank conflicts on column-ish A reads, keeps 16B align

__global__ void __launch_bounds__(512, 1) k_trunk(const float* __restrict__ Qg,
                                                  const float* __restrict__ Kg,
                                                  const float* __restrict__ Vg,
                                                  float* __restrict__ outg) {
    extern __shared__ float sm[];
    float* sS  = sm;                      // 4096
    float* sA  = sm + 4096;               // 128*68 = 8704
    float* sK  = sA + 8704;               // 8192
    float* sT1 = sK + 8192;               // 8192
    float* sT2 = sS;                      // alias

    const int tid = threadIdx.x;
    const long t = blockIdx.x;

    // load S (all CTAs, hits L2)
    for (int i = tid; i < 1024; i += 512)
        ((float4*)sS)[i] = ((const float4*)g_S)[i];

    // load V -> sA (stride 68), K -> sK
    const float4* V4 = (const float4*)Vg + t * 2048;
    const float4* K4 = (const float4*)Kg + t * 2048;
    for (int i = tid; i < 2048; i += 512) {
        const float4 v = V4[i];
        const int row = i >> 4, col = (i & 15) << 2;
        *(float4*)&sA[row * SA_STRIDE + col] = v;
        ((float4*)sK)[i] = K4[i];
    }
    __syncthreads();

    const int ty = tid >> 3, tx = tid & 7;
    const int r0 = ty * 2;        // 64 groups * 2 = 128 rows
    const int c0 = tx * 8;        // 8 groups * 8 = 64 cols

    // ---- GEMM1: T1[r][e] = sum_d V[r][d] * S[d][e] ----
    {
        unsigned long long a1[2][4];
#pragma unroll
        for (int i = 0; i < 2; ++i)
#pragma unroll
            for (int j = 0; j < 4; ++j) a1[i][j] = 0ull;

#pragma unroll 8
        for (int k = 0; k < 64; ++k) {
            const float x0 = sA[(r0 + 0) * SA_STRIDE + k];
            const float x1 = sA[(r0 + 1) * SA_STRIDE + k];
            const unsigned long long pa0 = bcast2(x0);
            const unsigned long long pa1 = bcast2(x1);
            const ulonglong2 b01 = *(const ulonglong2*)&sS[k * 64 + c0];
            const ulonglong2 b23 = *(const ulonglong2*)&sS[k * 64 + c0 + 4];
            f2(a1[0][0], pa0, b01.x); f2(a1[0][1], pa0, b01.y);
            f2(a1[0][2], pa0, b23.x); f2(a1[0][3], pa0, b23.y);
            f2(a1[1][0], pa1, b01.x); f2(a1[1][1], pa1, b01.y);
            f2(a1[1][2], pa1, b23.x); f2(a1[1][3], pa1, b23.y);
        }
#pragma unroll
        for (int i = 0; i < 2; ++i) {
            *(ulonglong2*)&sT1[(r0 + i) * 64 + c0]     = make_ulonglong2(a1[i][0], a1[i][1]);
            *(ulonglong2*)&sT1[(r0 + i) * 64 + c0 + 4] = make_ulonglong2(a1[i][2], a1[i][3]);
        }
    }
    __syncthreads();

    // load Q -> sA (V is dead), overlapped with GEMM2 below
    const float4* Q4 = (const float4*)Qg + t * 2048;
    for (int i = tid; i < 2048; i += 512) {
        const float4 v = Q4[i];
        const int row = i >> 4, col = (i & 15) << 2;
        *(float4*)&sA[row * SA_STRIDE + col] = v;
    }

    // ---- GEMM2: T2[m][n] = sum_k K[k][m] * T1[k][n] ----
    {
        const int m0 = (tid >> 4) * 2;   // 32 groups * 2 = 64
        const int n0 = (tid & 15) * 4;   // 16 groups * 4 = 64
        unsigned long long a2[2][2];
        a2[0][0] = a2[0][1] = a2[1][0] = a2[1][1] = 0ull;

#pragma unroll 8
        for (int k = 0; k < 128; ++k) {
            const float2 a = *(const float2*)&sK[k * 64 + m0];
            const unsigned long long pa0 = bcast2(a.x);
            const unsigned long long pa1 = bcast2(a.y);
            const ulonglong2 b = *(const ulonglong2*)&sT1[k * 64 + n0];
            f2(a2[0][0], pa0, b.x); f2(a2[0][1], pa0, b.y);
            f2(a2[1][0], pa1, b.x); f2(a2[1][1], pa1, b.y);
        }
        // sS is dead (GEMM1 synced) -> write T2 into its space
        *(ulonglong2*)&sT2[(m0 + 0) * 64 + n0] = make_ulonglong2(a2[0][0], a2[0][1]);
        *(ulonglong2*)&sT2[(m0 + 1) * 64 + n0] = make_ulonglong2(a2[1][0], a2[1][1]);
    }
    __syncthreads();

    // ---- GEMM3: out[r][e] = sum_d Q[r][d] * T2[d][e] ----
    {
        unsigned long long a3[2][4];
#pragma unroll
        for (int i = 0; i < 2; ++i)
#pragma unroll
            for (int j = 0; j < 4; ++j) a3[i][j] = 0ull;

#pragma unroll 8
        for (int k = 0; k < 64; ++k) {
            const float x0 = sA[(r0 + 0) * SA_STRIDE + k];
            const float x1 = sA[(r0 + 1) * SA_STRIDE + k];
            const unsigned long long pa0 = bcast2(x0);
            const unsigned long long pa1 = bcast2(x1);
            const ulonglong2 b01 = *(const ulonglong2*)&sT2[k * 64 + c0];
            const ulonglong2 b23 = *(const ulonglong2*)&sT2[k * 64 + c0 + 4];
            f2(a3[0][0], pa0, b01.x); f2(a3[0][1], pa0, b01.y);
            f2(a3[0][2], pa0, b23.x); f2(a3[0][3], pa0, b23.y);
            f2(a3[1][0], pa1, b01.x); f2(a3[1][1], pa1, b01.y);
            f2(a3[1][2], pa1, b23.x); f2(a3[1][3], pa1, b23.y);
        }
        float* outp = outg + t * (TRUNK * D);
#pragma unroll
        for (int i = 0; i < 2; ++i) {
            *(ulonglong2*)&outp[(r0 + i) * 64 + c0]     = make_ulonglong2(a3[i][0], a3[i][1]);
            *(ulonglong2*)&outp[(r0 + i) * 64 + c0 + 4] = make_ulonglong2(a3[i][2], a3[i][3]);
        }
    }
}

#define SMEM3_BYTES ((4096 + 128 * SA_STRIDE + 8192 + 8192) * 4)

extern "C" void kernel_launch(void* const* d_in, const int* in_sizes, int n_in,
                              void* d_out, int out_size) {
    const float* Q = (const float*)d_in[0];
    const float* K = (const float*)d_in[1];
    const float* V = (const float*)d_in[2];
    float* out = (float*)d_out;
    const int N = in_sizes[0] / D;     // 262144
    const int T = N / TRUNK;           // 2048

    cudaFuncSetAttribute(k_trunk, cudaFuncAttributeMaxDynamicSharedMemorySize,
                         SMEM3_BYTES);

    k_partialS<<<NBLK1, 256>>>(K, V, N);
    k_reduceS<<<16, 256>>>();
    k_trunk<<<T, 512, SMEM3_BYTES>>>(Q, K, V, out);
}

// round 2
// speedup vs baseline: 2.1738x; 2.1738x over previous
#include <cuda_runtime.h>

// LinearAttentionTriton restructured:
//   M_t = K_t^T V_t          (64x64 per trunk, K-dim 128)   -- kernel A
//   S   = sum_t M_t^T        (64x64 global)                 -- kernels B1/B2 (deterministic tree)
//   out_t = Q_t @ (M_t @ S)  (128x64 per trunk)             -- kernel C
//
// N = 262144, D = 64, TRUNK = 128, T = 2048.
// Total MACs: 2.68e9 (vs 4.3e9 for the naive chain).

#define D 64
#define TRUNK 128
#define T_TRUNKS 2048
#define B1_BLOCKS 128   // stage-1 reduce blocks (16 trunks each)

// device-global scratch (no cudaMalloc allowed)
__device__ __align__(16) float g_S[D * D];
__device__ __align__(16) float g_part[T_TRUNKS * D * D];   // per-trunk M_t (33.5 MB)
__device__ __align__(16) float g_red[B1_BLOCKS * D * D];   // stage-1 partials (2 MB)

// ---------------- f32x2 helpers (Blackwell packed fp32 FMA) ----------------
__device__ __forceinline__ unsigned long long bcast2(float x) {
    unsigned long long r;
    asm("mov.b64 %0, {%1, %1};" : "=l"(r) : "f"(x));
    return r;
}
__device__ __forceinline__ void f2(unsigned long long& d,
                                   unsigned long long a,
                                   unsigned long long b) {
    asm("fma.rn.f32x2 %0, %1, %2, %0;" : "+l"(d) : "l"(a), "l"(b));
}

// ---------------- Kernel A: M_t = K_t^T V_t ----------------
// grid = T_TRUNKS, block = 128, dyn smem 64 KB (3 CTAs/SM).
// Per-thread 4x8 tile: d0 = (tid>>3)*4 (rows of M), e0 = (tid&7)*8 (cols).
__global__ void __launch_bounds__(128) kA(const float* __restrict__ Kg,
                                          const float* __restrict__ Vg) {
    extern __shared__ float smA[];
    float* sK = smA;            // 128*64
    float* sV = smA + 8192;     // 128*64

    const int tid = threadIdx.x;
    const long t = blockIdx.x;

    const float4* K4 = (const float4*)Kg + t * 2048;
    const float4* V4 = (const float4*)Vg + t * 2048;
#pragma unroll
    for (int i = tid; i < 2048; i += 128) {
        ((float4*)sK)[i] = K4[i];
        ((float4*)sV)[i] = V4[i];
    }
    __syncthreads();

    const int d0 = (tid >> 3) * 4;
    const int e0 = (tid & 7) * 8;

    unsigned long long acc[4][4];
#pragma unroll
    for (int i = 0; i < 4; ++i)
#pragma unroll
        for (int j = 0; j < 4; ++j) acc[i][j] = 0ull;

#pragma unroll 4
    for (int r = 0; r < TRUNK; ++r) {
        const float4 a = *(const float4*)&sK[r * 64 + d0];
        const ulonglong2 b01 = *(const ulonglong2*)&sV[r * 64 + e0];
        const ulonglong2 b23 = *(const ulonglong2*)&sV[r * 64 + e0 + 4];
        const unsigned long long pa0 = bcast2(a.x);
        const unsigned long long pa1 = bcast2(a.y);
        const unsigned long long pa2 = bcast2(a.z);
        const unsigned long long pa3 = bcast2(a.w);
        f2(acc[0][0], pa0, b01.x); f2(acc[0][1], pa0, b01.y);
        f2(acc[0][2], pa0, b23.x); f2(acc[0][3], pa0, b23.y);
        f2(acc[1][0], pa1, b01.x); f2(acc[1][1], pa1, b01.y);
        f2(acc[1][2], pa1, b23.x); f2(acc[1][3], pa1, b23.y);
        f2(acc[2][0], pa2, b01.x); f2(acc[2][1], pa2, b01.y);
        f2(acc[2][2], pa2, b23.x); f2(acc[2][3], pa2, b23.y);
        f2(acc[3][0], pa3, b01.x); f2(acc[3][1], pa3, b01.y);
        f2(acc[3][2], pa3, b23.x); f2(acc[3][3], pa3, b23.y);
    }

    float* dst = g_part + t * 4096;
#pragma unroll
    for (int i = 0; i < 4; ++i) {
        *(ulonglong2*)&dst[(d0 + i) * 64 + e0]     = make_ulonglong2(acc[i][0], acc[i][1]);
        *(ulonglong2*)&dst[(d0 + i) * 64 + e0 + 4] = make_ulonglong2(acc[i][2], acc[i][3]);
    }
}

// ---------------- Kernel B1: partial sums of M over trunk groups ----------------
__global__ void __launch_bounds__(256) kB1() {
    const int blk = blockIdx.x;          // 128 blocks, 16 trunks each
    const int tid = threadIdx.x;
    const float* src = g_part + (long)blk * 16 * 4096;
#pragma unroll
    for (int i = 0; i < 16; ++i) {
        const int x = tid + i * 256;
        float s = 0.0f;
#pragma unroll
        for (int tt = 0; tt < 16; ++tt) s += src[tt * 4096 + x];
        g_red[blk * 4096 + x] = s;
    }
}

// ---------------- Kernel B2: S[d][e] = sum_b red[b][e*64+d] (transpose) ----------------
__global__ void __launch_bounds__(256) kB2() {
    const int idx = blockIdx.x * 256 + threadIdx.x;   // 4096 threads
    const int d = idx & 63, e = idx >> 6;
    float s = 0.0f;
#pragma unroll 8
    for (int b = 0; b < B1_BLOCKS; ++b) s += g_red[b * 4096 + idx];  // idx = e*64+d
    g_S[d * 64 + e] = s;
}

// ---------------- Kernel C: out_t = Q_t @ (M_t @ S) ----------------
// grid = T_TRUNKS, block = 256, dyn smem 84 KB (2 CTAs/SM).
#define QT_STR 132   // Q^T stride: 16B-aligned, bank-conflict-free LDS.128 rows

__global__ void __launch_bounds__(256, 2) kC(const float* __restrict__ Qg,
                                             float* __restrict__ outg) {
    extern __shared__ float smC[];
    float* sS  = smC;            // 4096
    float* sM  = smC + 4096;     // 64*68 = 4352 (padded rows)
    float* sR  = smC + 8448;     // 4096
    float* sQt = smC + 12544;    // 64*132 = 8448  -> total 20992 floats

    const int tid = threadIdx.x;
    const long t = blockIdx.x;

    // prefetch Q into registers (long-latency, overlaps everything below)
    const float4* Q4 = (const float4*)Qg + t * 2048;
    float4 q[8];
#pragma unroll
    for (int j = 0; j < 8; ++j) q[j] = Q4[tid + j * 256];

    // stage S and M_t
#pragma unroll
    for (int i = tid; i < 1024; i += 256)
        ((float4*)sS)[i] = ((const float4*)g_S)[i];
    const float4* M4 = (const float4*)g_part + t * 1024;
#pragma unroll
    for (int i = tid; i < 1024; i += 256) {
        const float4 v = M4[i];
        const int row = i >> 4, col = (i & 15) << 2;
        *(float4*)&sM[row * 68 + col] = v;
    }
    __syncthreads();

    // ---- R = M_t @ S  (64x64, K=64), 2x8 tile per thread ----
    {
        const int m0 = (tid >> 3) * 2;
        const int e0 = (tid & 7) * 8;
        unsigned long long a1[2][4];
#pragma unroll
        for (int i = 0; i < 2; ++i)
#pragma unroll
            for (int j = 0; j < 4; ++j) a1[i][j] = 0ull;

#pragma unroll 8
        for (int k = 0; k < 64; ++k) {
            const float x0 = sM[m0 * 68 + k];
            const float x1 = sM[(m0 + 1) * 68 + k];
            const unsigned long long pa0 = bcast2(x0);
            const unsigned long long pa1 = bcast2(x1);
            const ulonglong2 b01 = *(const ulonglong2*)&sS[k * 64 + e0];
            const ulonglong2 b23 = *(const ulonglong2*)&sS[k * 64 + e0 + 4];
            f2(a1[0][0], pa0, b01.x); f2(a1[0][1], pa0, b01.y);
            f2(a1[0][2], pa0, b23.x); f2(a1[0][3], pa0, b23.y);
            f2(a1[1][0], pa1, b01.x); f2(a1[1][1], pa1, b01.y);
            f2(a1[1][2], pa1, b23.x); f2(a1[1][3], pa1, b23.y);
        }
#pragma unroll
        for (int i = 0; i < 2; ++i) {
            *(ulonglong2*)&sR[(m0 + i) * 64 + e0]     = make_ulonglong2(a1[i][0], a1[i][1]);
            *(ulonglong2*)&sR[(m0 + i) * 64 + e0 + 4] = make_ulonglong2(a1[i][2], a1[i][3]);
        }
    }

    // store Q^T (registers -> smem, transposed)
#pragma unroll
    for (int j = 0; j < 8; ++j) {
        const int i = tid + j * 256;
        const int row = i >> 4, col = (i & 15) << 2;
        sQt[(col + 0) * QT_STR + row] = q[j].x;
        sQt[(col + 1) * QT_STR + row] = q[j].y;
        sQt[(col + 2) * QT_STR + row] = q[j].z;
        sQt[(col + 3) * QT_STR + row] = q[j].w;
    }
    __syncthreads();

    // ---- out = Q_t @ R  (128x64, K=64), 4x8 tile per thread ----
    {
        const int r0 = (tid >> 3) * 4;
        const int c0 = (tid & 7) * 8;
        unsigned long long a3[4][4];
#pragma unroll
        for (int i = 0; i < 4; ++i)
#pragma unroll
            for (int j = 0; j < 4; ++j) a3[i][j] = 0ull;

#pragma unroll 4
        for (int k = 0; k < 64; ++k) {
            const float4 a = *(const float4*)&sQt[k * QT_STR + r0];  // Q[r0..r0+3][k]
            const ulonglong2 b01 = *(const ulonglong2*)&sR[k * 64 + c0];
            const ulonglong2 b23 = *(const ulonglong2*)&sR[k * 64 + c0 + 4];
            const unsigned long long pa0 = bcast2(a.x);
            const unsigned long long pa1 = bcast2(a.y);
            const unsigned long long pa2 = bcast2(a.z);
            const unsigned long long pa3 = bcast2(a.w);
            f2(a3[0][0], pa0, b01.x); f2(a3[0][1], pa0, b01.y);
            f2(a3[0][2], pa0, b23.x); f2(a3[0][3], pa0, b23.y);
            f2(a3[1][0], pa1, b01.x); f2(a3[1][1], pa1, b01.y);
            f2(a3[1][2], pa1, b23.x); f2(a3[1][3], pa1, b23.y);
            f2(a3[2][0], pa2, b01.x); f2(a3[2][1], pa2, b01.y);
            f2(a3[2][2], pa2, b23.x); f2(a3[2][3], pa2, b23.y);
            f2(a3[3][0], pa3, b01.x); f2(a3[3][1], pa3, b01.y);
            f2(a3[3][2], pa3, b23.x); f2(a3[3][3], pa3, b23.y);
        }
        float* outp = outg + t * (TRUNK * D);
#pragma unroll
        for (int i = 0; i < 4; ++i) {
            *(ulonglong2*)&outp[(r0 + i) * 64 + c0]     = make_ulonglong2(a3[i][0], a3[i][1]);
            *(ulonglong2*)&outp[(r0 + i) * 64 + c0 + 4] = make_ulonglong2(a3[i][2], a3[i][3]);
        }
    }
}

#define SMEM_A_BYTES (2 * 128 * 64 * 4)              // 64 KB
#define SMEM_C_BYTES ((4096 + 4352 + 4096 + 64 * QT_STR) * 4)   // 83968 B

extern "C" void kernel_launch(void* const* d_in, const int* in_sizes, int n_in,
                              void* d_out, int out_size) {
    const float* Q = (const float*)d_in[0];
    const float* K = (const float*)d_in[1];
    const float* V = (const float*)d_in[2];
    float* out = (float*)d_out;

    cudaFuncSetAttribute(kA, cudaFuncAttributeMaxDynamicSharedMemorySize, SMEM_A_BYTES);
    cudaFuncSetAttribute(kC, cudaFuncAttributeMaxDynamicSharedMemorySize, SMEM_C_BYTES);

    kA<<<T_TRUNKS, 128, SMEM_A_BYTES>>>(K, V);
    kB1<<<B1_BLOCKS, 256>>>();
    kB2<<<16, 256>>>();
    kC<<<T_TRUNKS, 256, SMEM_C_BYTES>>>(Q, out);
}

// round 3
// speedup vs baseline: 2.6172x; 1.2040x over previous
#include <cuda_runtime.h>

// LinearAttentionTriton:
//   M_t = K_t^T V_t   (64x64 per trunk)           -- kA
//   S   = sum_t M_t^T (64x64 global)              -- kB1/kB2 (deterministic)
//   R_t = M_t @ S                                  -- kR
//   out_t = Q_t @ R_t                              -- kO
// N = 262144, D = 64, TRUNK = 128, T = 2048. 2.68e9 MACs total.

#define D 64
#define TRUNK 128
#define T_TRUNKS 2048
#define B1_BLOCKS 128

__device__ __align__(16) float g_S[D * D];
__device__ __align__(16) float g_part[T_TRUNKS * D * D];   // M_t, 33.5 MB
__device__ __align__(16) float g_R[T_TRUNKS * D * D];      // R_t, 33.5 MB
__device__ __align__(16) float g_red[B1_BLOCKS * D * D];

// ---------------- f32x2 helpers ----------------
__device__ __forceinline__ unsigned long long bcast2(float x) {
    unsigned long long r;
    asm("mov.b64 %0, {%1, %1};" : "=l"(r) : "f"(x));
    return r;
}
__device__ __forceinline__ void f2(unsigned long long& d,
                                   unsigned long long a,
                                   unsigned long long b) {
    asm("fma.rn.f32x2 %0, %1, %2, %0;" : "+l"(d) : "l"(a), "l"(b));
}

// ---------------- kA: M_t = K_t^T V_t ----------------
// grid 2048, block 64, smem 64 KB (3 CTAs/SM). 8x8 tile per thread.
__global__ void __launch_bounds__(64) kA(const float* __restrict__ Kg,
                                         const float* __restrict__ Vg) {
    extern __shared__ float smA[];
    float* sK = smA;          // 128*64
    float* sV = smA + 8192;   // 128*64

    const int tid = threadIdx.x;
    const long t = blockIdx.x;

    const float4* K4 = (const float4*)Kg + t * 2048;
    const float4* V4 = (const float4*)Vg + t * 2048;
#pragma unroll 4
    for (int i = tid; i < 2048; i += 64) {
        ((float4*)sK)[i] = K4[i];
        ((float4*)sV)[i] = V4[i];
    }
    __syncthreads();

    const int d0 = (tid >> 3) * 8;   // 8 groups * 8 = 64 rows of M
    const int e0 = (tid & 7) * 8;    // 8 groups * 8 = 64 cols

    unsigned long long acc[8][4];
#pragma unroll
    for (int i = 0; i < 8; ++i)
#pragma unroll
        for (int j = 0; j < 4; ++j) acc[i][j] = 0ull;

#pragma unroll 4
    for (int r = 0; r < TRUNK; ++r) {
        const float4 a03 = *(const float4*)&sK[r * 64 + d0];
        const float4 a47 = *(const float4*)&sK[r * 64 + d0 + 4];
        const ulonglong2 b01 = *(const ulonglong2*)&sV[r * 64 + e0];
        const ulonglong2 b23 = *(const ulonglong2*)&sV[r * 64 + e0 + 4];
        const unsigned long long pb[4] = {b01.x, b01.y, b23.x, b23.y};
        const float av[8] = {a03.x, a03.y, a03.z, a03.w, a47.x, a47.y, a47.z, a47.w};
#pragma unroll
        for (int i = 0; i < 8; ++i) {
            const unsigned long long pa = bcast2(av[i]);
            f2(acc[i][0], pa, pb[0]); f2(acc[i][1], pa, pb[1]);
            f2(acc[i][2], pa, pb[2]); f2(acc[i][3], pa, pb[3]);
        }
    }

    float* dst = g_part + t * 4096;
#pragma unroll
    for (int i = 0; i < 8; ++i) {
        *(ulonglong2*)&dst[(d0 + i) * 64 + e0]     = make_ulonglong2(acc[i][0], acc[i][1]);
        *(ulonglong2*)&dst[(d0 + i) * 64 + e0 + 4] = make_ulonglong2(acc[i][2], acc[i][3]);
    }
}

// ---------------- kB1/kB2: deterministic reduction to S ----------------
__global__ void __launch_bounds__(256) kB1() {
    const int blk = blockIdx.x;
    const int tid = threadIdx.x;
    const float* src = g_part + (long)blk * 16 * 4096;
#pragma unroll
    for (int i = 0; i < 16; ++i) {
        const int x = tid + i * 256;
        float s = 0.0f;
#pragma unroll
        for (int tt = 0; tt < 16; ++tt) s += src[tt * 4096 + x];
        g_red[blk * 4096 + x] = s;
    }
}
__global__ void __launch_bounds__(256) kB2() {
    const int idx = blockIdx.x * 256 + threadIdx.x;   // idx = e*64+d
    const int d = idx & 63, e = idx >> 6;
    float s = 0.0f;
#pragma unroll 8
    for (int b = 0; b < B1_BLOCKS; ++b) s += g_red[b * 4096 + idx];
    g_S[d * 64 + e] = s;
}

// ---------------- kR: R_t = M_t @ S ----------------
// grid 2048, block 64, smem 33 KB (6 CTAs/SM). 8x8 tile.
// sM padded stride 65: column reads hit distinct banks (8*65 % 32 = 8).
__global__ void __launch_bounds__(64) kR(float* __restrict__ dummy) {
    extern __shared__ float smR[];
    float* sS = smR;          // 64*64
    float* sM = smR + 4096;   // 64*65

    const int tid = threadIdx.x;
    const long t = blockIdx.x;

#pragma unroll 4
    for (int i = tid; i < 1024; i += 64)
        ((float4*)sS)[i] = ((const float4*)g_S)[i];

    const float4* M4 = (const float4*)(g_part) + t * 1024;
#pragma unroll 4
    for (int i = tid; i < 1024; i += 64) {
        const float4 v = M4[i];
        const int row = i >> 4, col = (i & 15) << 2;
        sM[row * 65 + col + 0] = v.x;
        sM[row * 65 + col + 1] = v.y;
        sM[row * 65 + col + 2] = v.z;
        sM[row * 65 + col + 3] = v.w;
    }
    __syncthreads();

    const int m0 = (tid >> 3) * 8;
    const int e0 = (tid & 7) * 8;

    unsigned long long acc[8][4];
#pragma unroll
    for (int i = 0; i < 8; ++i)
#pragma unroll
        for (int j = 0; j < 4; ++j) acc[i][j] = 0ull;

#pragma unroll 2
    for (int k = 0; k < 64; ++k) {
        const ulonglong2 b01 = *(const ulonglong2*)&sS[k * 64 + e0];
        const ulonglong2 b23 = *(const ulonglong2*)&sS[k * 64 + e0 + 4];
        const unsigned long long pb[4] = {b01.x, b01.y, b23.x, b23.y};
#pragma unroll
        for (int i = 0; i < 8; ++i) {
            const unsigned long long pa = bcast2(sM[(m0 + i) * 65 + k]);
            f2(acc[i][0], pa, pb[0]); f2(acc[i][1], pa, pb[1]);
            f2(acc[i][2], pa, pb[2]); f2(acc[i][3], pa, pb[3]);
        }
    }

    float* dst = g_R + t * 4096;
#pragma unroll
    for (int i = 0; i < 8; ++i) {
        *(ulonglong2*)&dst[(m0 + i) * 64 + e0]     = make_ulonglong2(acc[i][0], acc[i][1]);
        *(ulonglong2*)&dst[(m0 + i) * 64 + e0 + 4] = make_ulonglong2(acc[i][2], acc[i][3]);
    }
}

// ---------------- kO: out_t = Q_t @ R_t ----------------
// grid 2048, block 64, smem 48 KB (4 CTAs/SM). 8x16 tile per thread.
// sQ XOR-swizzled: element (row, col) at row*64 + (col ^ ((row>>3 & 7)<<2)).
// Column reads (fixed k, 8 row-groups) -> 8 distinct banks, 1 cyc each.
__global__ void __launch_bounds__(64) kO(const float* __restrict__ Qg,
                                         float* __restrict__ outg) {
    extern __shared__ float smO[];
    float* sQ = smO;          // 128*64 swizzled
    float* sR = smO + 8192;   // 64*64

    const int tid = threadIdx.x;
    const long t = blockIdx.x;

    const float4* R4 = (const float4*)(g_R) + t * 1024;
#pragma unroll 4
    for (int i = tid; i < 1024; i += 64)
        ((float4*)sR)[i] = R4[i];

    const float4* Q4 = (const float4*)Qg + t * 2048;
#pragma unroll 4
    for (int i = tid; i < 2048; i += 64) {
        const float4 v = Q4[i];
        const int row = i >> 4;
        const int col = (i & 15) << 2;
        const int sw = ((row >> 3) & 7) << 2;
        sQ[row * 64 + ((col + 0) ^ sw)] = v.x;
        sQ[row * 64 + ((col + 1) ^ sw)] = v.y;
        sQ[row * 64 + ((col + 2) ^ sw)] = v.z;
        sQ[row * 64 + ((col + 3) ^ sw)] = v.w;
    }
    __syncthreads();

    const int r0 = (tid >> 2) * 8;    // 16 groups * 8 = 128 rows
    const int c0 = (tid & 3) * 16;    // 4 groups * 16 = 64 cols
    const int sw = ((r0 >> 3) & 7) << 2;   // constant per thread

    unsigned long long acc[8][8];
#pragma unroll
    for (int i = 0; i < 8; ++i)
#pragma unroll
        for (int j = 0; j < 8; ++j) acc[i][j] = 0ull;

#pragma unroll 2
    for (int k = 0; k < 64; ++k) {
        const int kx = k ^ sw;
        // B: 16 floats of R row k
        const ulonglong2 b01 = *(const ulonglong2*)&sR[k * 64 + c0];
        const ulonglong2 b23 = *(const ulonglong2*)&sR[k * 64 + c0 + 4];
        const ulonglong2 b45 = *(const ulonglong2*)&sR[k * 64 + c0 + 8];
        const ulonglong2 b67 = *(const ulonglong2*)&sR[k * 64 + c0 + 12];
        const unsigned long long pb[8] = {b01.x, b01.y, b23.x, b23.y,
                                          b45.x, b45.y, b67.x, b67.y};
#pragma unroll
        for (int i = 0; i < 8; ++i) {
            const unsigned long long pa = bcast2(sQ[(r0 + i) * 64 + kx]);
            f2(acc[i][0], pa, pb[0]); f2(acc[i][1], pa, pb[1]);
            f2(acc[i][2], pa, pb[2]); f2(acc[i][3], pa, pb[3]);
            f2(acc[i][4], pa, pb[4]); f2(acc[i][5], pa, pb[5]);
            f2(acc[i][6], pa, pb[6]); f2(acc[i][7], pa, pb[7]);
        }
    }

    float* outp = outg + t * (TRUNK * D);
#pragma unroll
    for (int i = 0; i < 8; ++i) {
        float* orow = &outp[(r0 + i) * 64 + c0];
        *(ulonglong2*)&orow[0]  = make_ulonglong2(acc[i][0], acc[i][1]);
        *(ulonglong2*)&orow[4]  = make_ulonglong2(acc[i][2], acc[i][3]);
        *(ulonglong2*)&orow[8]  = make_ulonglong2(acc[i][4], acc[i][5]);
        *(ulonglong2*)&orow[12] = make_ulonglong2(acc[i][6], acc[i][7]);
    }
}

#define SMEM_A_BYTES (2 * 128 * 64 * 4)          // 65536
#define SMEM_R_BYTES ((4096 + 64 * 65) * 4)      // 33024
#define SMEM_O_BYTES ((8192 + 4096) * 4)         // 49152

extern "C" void kernel_launch(void* const* d_in, const int* in_sizes, int n_in,
                              void* d_out, int out_size) {
    const float* Q = (const float*)d_in[0];
    const float* K = (const float*)d_in[1];
    const float* V = (const float*)d_in[2];
    float* out = (float*)d_out;

    cudaFuncSetAttribute(kA, cudaFuncAttributeMaxDynamicSharedMemorySize, SMEM_A_BYTES);
    cudaFuncSetAttribute(kR, cudaFuncAttributeMaxDynamicSharedMemorySize, SMEM_R_BYTES);
    cudaFuncSetAttribute(kO, cudaFuncAttributeMaxDynamicSharedMemorySize, SMEM_O_BYTES);

    kA<<<T_TRUNKS, 64, SMEM_A_BYTES>>>(K, V);
    kB1<<<B1_BLOCKS, 256>>>();
    kB2<<<16, 256>>>();
    kR<<<T_TRUNKS, 64, SMEM_R_BYTES>>>(nullptr);
    kO<<<T_TRUNKS, 64, SMEM_O_BYTES>>>(Q, out);
}

// round 4
// speedup vs baseline: 2.6696x; 1.0200x over previous
#include <cuda_runtime.h>

// LinearAttentionTriton:
//   M_t = K_t^T V_t   (64x64 per trunk)     -- kA (split-K, 128 thr)
//   S   = sum_t M_t^T (64x64 global)        -- kB1/kB2 (deterministic)
//   out_t = Q_t @ (M_t @ S) = (Q_t @ M_t) @ S   -- kQO (fused, 128 thr)
// N = 262144, D = 64, TRUNK = 128, T = 2048. 2.68e9 MACs total.

#define D 64
#define TRUNK 128
#define T_TRUNKS 2048
#define B1_BLOCKS 128

__device__ __align__(16) float g_S[D * D];
__device__ __align__(16) float g_part[T_TRUNKS * D * D];   // M_t, 33.5 MB
__device__ __align__(16) float g_red[B1_BLOCKS * D * D];

// ---------------- f32x2 helpers ----------------
__device__ __forceinline__ unsigned long long bcast2(float x) {
    unsigned long long r;
    asm("mov.b64 %0, {%1, %1};" : "=l"(r) : "f"(x));
    return r;
}
__device__ __forceinline__ void f2(unsigned long long& d,
                                   unsigned long long a,
                                   unsigned long long b) {
    asm("fma.rn.f32x2 %0, %1, %2, %0;" : "+l"(d) : "l"(a), "l"(b));
}
__device__ __forceinline__ void a2(unsigned long long& d, unsigned long long a) {
    asm("add.rn.f32x2 %0, %0, %1;" : "+l"(d) : "l"(a));
}

// ---------------- kA: M_t = K_t^T V_t (split-K over 2 thread-halves) ----------------
// grid 2048, block 128, smem 64 KB (3 CTAs/SM -> 12 warps).
__global__ void __launch_bounds__(128) kA(const float* __restrict__ Kg,
                                          const float* __restrict__ Vg) {
    extern __shared__ float smA[];
    float* sK = smA;          // 128*64
    float* sV = smA + 8192;   // 128*64

    const int tid = threadIdx.x;
    const long t = blockIdx.x;

    const float4* K4 = (const float4*)Kg + t * 2048;
    const float4* V4 = (const float4*)Vg + t * 2048;
#pragma unroll
    for (int i = tid; i < 2048; i += 128) {
        ((float4*)sK)[i] = K4[i];
        ((float4*)sV)[i] = V4[i];
    }
    __syncthreads();

    const int half = tid >> 6;       // 0 or 1: K-rows [0,64) or [64,128)
    const int lt = tid & 63;
    const int d0 = (lt >> 3) * 8;
    const int e0 = (lt & 7) * 8;

    unsigned long long acc[8][4];
#pragma unroll
    for (int i = 0; i < 8; ++i)
#pragma unroll
        for (int j = 0; j < 4; ++j) acc[i][j] = 0ull;

    const int rbase = half * 64;
#pragma unroll 4
    for (int rr = 0; rr < 64; ++rr) {
        const int r = rbase + rr;
        const float4 a03 = *(const float4*)&sK[r * 64 + d0];
        const float4 a47 = *(const float4*)&sK[r * 64 + d0 + 4];
        const ulonglong2 b01 = *(const ulonglong2*)&sV[r * 64 + e0];
        const ulonglong2 b23 = *(const ulonglong2*)&sV[r * 64 + e0 + 4];
        const unsigned long long pb[4] = {b01.x, b01.y, b23.x, b23.y};
        const float av[8] = {a03.x, a03.y, a03.z, a03.w, a47.x, a47.y, a47.z, a47.w};
#pragma unroll
        for (int i = 0; i < 8; ++i) {
            const unsigned long long pa = bcast2(av[i]);
            f2(acc[i][0], pa, pb[0]); f2(acc[i][1], pa, pb[1]);
            f2(acc[i][2], pa, pb[2]); f2(acc[i][3], pa, pb[3]);
        }
    }
    __syncthreads();   // sK/sV reads done; sK space reusable

    // cross-half reduction: half 1 stores, half 0 adds + writes out
    ulonglong2* sRed = (ulonglong2*)sK;   // 64 thr * 16 u2 = 16 KB
    if (half == 1) {
#pragma unroll
        for (int i = 0; i < 8; ++i) {
            sRed[(i * 2 + 0) * 64 + lt] = make_ulonglong2(acc[i][0], acc[i][1]);
            sRed[(i * 2 + 1) * 64 + lt] = make_ulonglong2(acc[i][2], acc[i][3]);
        }
    }
    __syncthreads();
    if (half == 0) {
        float* dst = g_part + t * 4096;
#pragma unroll
        for (int i = 0; i < 8; ++i) {
            const ulonglong2 v0 = sRed[(i * 2 + 0) * 64 + lt];
            const ulonglong2 v1 = sRed[(i * 2 + 1) * 64 + lt];
            a2(acc[i][0], v0.x); a2(acc[i][1], v0.y);
            a2(acc[i][2], v1.x); a2(acc[i][3], v1.y);
            *(ulonglong2*)&dst[(d0 + i) * 64 + e0]     = make_ulonglong2(acc[i][0], acc[i][1]);
            *(ulonglong2*)&dst[(d0 + i) * 64 + e0 + 4] = make_ulonglong2(acc[i][2], acc[i][3]);
        }
    }
}

// ---------------- kB1/kB2: deterministic reduction to S ----------------
__global__ void __launch_bounds__(256) kB1() {
    const int blk = blockIdx.x;
    const int tid = threadIdx.x;
    const float* src = g_part + (long)blk * 16 * 4096;
#pragma unroll
    for (int i = 0; i < 16; ++i) {
        const int x = tid + i * 256;
        float s = 0.0f;
#pragma unroll
        for (int tt = 0; tt < 16; ++tt) s += src[tt * 4096 + x];
        g_red[blk * 4096 + x] = s;
    }
}
__global__ void __launch_bounds__(256) kB2() {
    const int idx = blockIdx.x * 256 + threadIdx.x;   // idx = e*64+d
    const int d = idx & 63, e = idx >> 6;
    float s = 0.0f;
#pragma unroll 8
    for (int b = 0; b < B1_BLOCKS; ++b) s += g_red[b * 4096 + idx];
    g_S[d * 64 + e] = s;
}

// ---------------- kQO: out_t = (Q_t @ M_t) @ S ----------------
// grid 2048, block 128, smem 64 KB (3 CTAs/SM -> 12 warps).
// sQ XOR-swizzled for column reads; P stored swizzled back into sQ's space.
__global__ void __launch_bounds__(128) kQO(const float* __restrict__ Qg,
                                           float* __restrict__ outg) {
    extern __shared__ float smQ[];
    float* sQ = smQ;           // 128*64 swizzled (later holds P swizzled)
    float* sM = smQ + 8192;    // 64*64
    float* sS = smQ + 12288;   // 64*64

    const int tid = threadIdx.x;
    const long t = blockIdx.x;

    const float4* M4 = (const float4*)g_part + t * 1024;
#pragma unroll
    for (int i = tid; i < 1024; i += 128) {
        ((float4*)sM)[i] = M4[i];
        ((float4*)sS)[i] = ((const float4*)g_S)[i];
    }

    const float4* Q4 = (const float4*)Qg + t * 2048;
#pragma unroll
    for (int i = tid; i < 2048; i += 128) {
        const float4 v = Q4[i];
        const int row = i >> 4;
        const int col = (i & 15) << 2;
        const int sw = ((row >> 3) & 7) << 2;
        sQ[row * 64 + ((col + 0) ^ sw)] = v.x;
        sQ[row * 64 + ((col + 1) ^ sw)] = v.y;
        sQ[row * 64 + ((col + 2) ^ sw)] = v.z;
        sQ[row * 64 + ((col + 3) ^ sw)] = v.w;
    }
    __syncthreads();

    const int r0 = (tid >> 3) * 8;   // 16 groups * 8 = 128 rows
    const int c0 = (tid & 7) * 8;    // 8 groups * 8 = 64 cols
    const int sw = ((r0 >> 3) & 7) << 2;

    // ---- GEMM1: P = Q_t @ M_t ----
    unsigned long long acc[8][4];
#pragma unroll
    for (int i = 0; i < 8; ++i)
#pragma unroll
        for (int j = 0; j < 4; ++j) acc[i][j] = 0ull;

#pragma unroll 2
    for (int k = 0; k < 64; ++k) {
        const int kx = k ^ sw;
        const ulonglong2 b01 = *(const ulonglong2*)&sM[k * 64 + c0];
        const ulonglong2 b23 = *(const ulonglong2*)&sM[k * 64 + c0 + 4];
        const unsigned long long pb[4] = {b01.x, b01.y, b23.x, b23.y};
#pragma unroll
        for (int i = 0; i < 8; ++i) {
            const unsigned long long pa = bcast2(sQ[(r0 + i) * 64 + kx]);
            f2(acc[i][0], pa, pb[0]); f2(acc[i][1], pa, pb[1]);
            f2(acc[i][2], pa, pb[2]); f2(acc[i][3], pa, pb[3]);
        }
    }
    __syncthreads();   // all sQ reads complete

    // store P swizzled into sQ's space (row-group swizzle = same scheme)
    {
        float pf[8];
#pragma unroll
        for (int i = 0; i < 8; ++i) {
            *(ulonglong2*)&pf[0] = make_ulonglong2(acc[i][0], acc[i][1]);
            *(ulonglong2*)&pf[4] = make_ulonglong2(acc[i][2], acc[i][3]);
            const int row = r0 + i;
#pragma unroll
            for (int c = 0; c < 8; ++c)
                sQ[row * 64 + ((c0 + c) ^ sw)] = pf[c];
        }
    }
    __syncthreads();

    // ---- GEMM2: out = P @ S ----
#pragma unroll
    for (int i = 0; i < 8; ++i)
#pragma unroll
        for (int j = 0; j < 4; ++j) acc[i][j] = 0ull;

#pragma unroll 2
    for (int k = 0; k < 64; ++k) {
        const int kx = k ^ sw;
        const ulonglong2 b01 = *(const ulonglong2*)&sS[k * 64 + c0];
        const ulonglong2 b23 = *(const ulonglong2*)&sS[k * 64 + c0 + 4];
        const unsigned long long pb[4] = {b01.x, b01.y, b23.x, b23.y};
#pragma unroll
        for (int i = 0; i < 8; ++i) {
            const unsigned long long pa = bcast2(sQ[(r0 + i) * 64 + kx]);
            f2(acc[i][0], pa, pb[0]); f2(acc[i][1], pa, pb[1]);
            f2(acc[i][2], pa, pb[2]); f2(acc[i][3], pa, pb[3]);
        }
    }

    float* outp = outg + t * (TRUNK * D);
#pragma unroll
    for (int i = 0; i < 8; ++i) {
        *(ulonglong2*)&outp[(r0 + i) * 64 + c0]     = make_ulonglong2(acc[i][0], acc[i][1]);
        *(ulonglong2*)&outp[(r0 + i) * 64 + c0 + 4] = make_ulonglong2(acc[i][2], acc[i][3]);
    }
}

#define SMEM_A_BYTES (2 * 128 * 64 * 4)                 // 65536
#define SMEM_QO_BYTES ((8192 + 4096 + 4096) * 4)        // 65536

extern "C" void kernel_launch(void* const* d_in, const int* in_sizes, int n_in,
                              void* d_out, int out_size) {
    const float* Q = (const float*)d_in[0];
    const float* K = (const float*)d_in[1];
    const float* V = (const float*)d_in[2];
    float* out = (float*)d_out;

    cudaFuncSetAttribute(kA, cudaFuncAttributeMaxDynamicSharedMemorySize, SMEM_A_BYTES);
    cudaFuncSetAttribute(kQO, cudaFuncAttributeMaxDynamicSharedMemorySize, SMEM_QO_BYTES);

    kA<<<T_TRUNKS, 128, SMEM_A_BYTES>>>(K, V);
    kB1<<<B1_BLOCKS, 256>>>();
    kB2<<<16, 256>>>();
    kQO<<<T_TRUNKS, 128, SMEM_QO_BYTES>>>(Q, out);
}

// round 5
// speedup vs baseline: 3.2042x; 1.2002x over previous
#include <cuda_runtime.h>

// LinearAttentionTriton:
//   M_t = K_t^T V_t   (64x64 per trunk)     -- kA (split-K x4, 256 thr)
//   S   = sum_t M_t^T (64x64 global)        -- kB1/kB2 (deterministic)
//   out_t = (Q_t @ M_t) @ S                 -- kQO (fused, 128 thr, 48 KB)
// N = 262144, D = 64, TRUNK = 128, T = 2048. 2.68e9 MACs total.

#define D 64
#define TRUNK 128
#define T_TRUNKS 2048
#define B1_BLOCKS 128

__device__ __align__(16) float g_S[D * D];
__device__ __align__(16) float g_part[T_TRUNKS * D * D];   // M_t, 33.5 MB
__device__ __align__(16) float g_red[B1_BLOCKS * D * D];

// ---------------- f32x2 helpers ----------------
__device__ __forceinline__ unsigned long long bcast2(float x) {
    unsigned long long r;
    asm("mov.b64 %0, {%1, %1};" : "=l"(r) : "f"(x));
    return r;
}
__device__ __forceinline__ void f2(unsigned long long& d,
                                   unsigned long long a,
                                   unsigned long long b) {
    asm("fma.rn.f32x2 %0, %1, %2, %0;" : "+l"(d) : "l"(a), "l"(b));
}
__device__ __forceinline__ void a2(unsigned long long& d, unsigned long long a) {
    asm("add.rn.f32x2 %0, %0, %1;" : "+l"(d) : "l"(a));
}

// ---------------- kA: M_t = K_t^T V_t (split-K over 4 thread-quarters) ----------------
// grid 2048, block 256, smem 64 KB (2 CTAs/SM -> 16 warps).
__global__ void __launch_bounds__(256, 2) kA(const float* __restrict__ Kg,
                                             const float* __restrict__ Vg) {
    extern __shared__ float smA[];
    float* sK = smA;          // 128*64
    float* sV = smA + 8192;   // 128*64

    const int tid = threadIdx.x;
    const long t = blockIdx.x;

    const float4* K4 = (const float4*)Kg + t * 2048;
    const float4* V4 = (const float4*)Vg + t * 2048;
#pragma unroll
    for (int i = tid; i < 2048; i += 256) {
        ((float4*)sK)[i] = K4[i];
        ((float4*)sV)[i] = V4[i];
    }
    __syncthreads();

    const int q  = tid >> 6;         // quarter: K-rows [q*32, q*32+32)
    const int lt = tid & 63;
    const int d0 = (lt >> 3) * 8;
    const int e0 = (lt & 7) * 8;

    unsigned long long acc[8][4];
#pragma unroll
    for (int i = 0; i < 8; ++i)
#pragma unroll
        for (int j = 0; j < 4; ++j) acc[i][j] = 0ull;

    const int rbase = q * 32;
#pragma unroll 4
    for (int rr = 0; rr < 32; ++rr) {
        const int r = rbase + rr;
        const float4 a03 = *(const float4*)&sK[r * 64 + d0];
        const float4 a47 = *(const float4*)&sK[r * 64 + d0 + 4];
        const ulonglong2 b01 = *(const ulonglong2*)&sV[r * 64 + e0];
        const ulonglong2 b23 = *(const ulonglong2*)&sV[r * 64 + e0 + 4];
        const unsigned long long pb[4] = {b01.x, b01.y, b23.x, b23.y};
        const float av[8] = {a03.x, a03.y, a03.z, a03.w, a47.x, a47.y, a47.z, a47.w};
#pragma unroll
        for (int i = 0; i < 8; ++i) {
            const unsigned long long pa = bcast2(av[i]);
            f2(acc[i][0], pa, pb[0]); f2(acc[i][1], pa, pb[1]);
            f2(acc[i][2], pa, pb[2]); f2(acc[i][3], pa, pb[3]);
        }
    }
    __syncthreads();   // all sK/sV reads done; smA reusable

    // quarters 1..3 park partials in smem (3 * 16 KB <= 64 KB)
    if (q > 0) {
        float* dst = smA + (q - 1) * 4096;
#pragma unroll
        for (int i = 0; i < 8; ++i) {
            *(ulonglong2*)&dst[(d0 + i) * 64 + e0]     = make_ulonglong2(acc[i][0], acc[i][1]);
            *(ulonglong2*)&dst[(d0 + i) * 64 + e0 + 4] = make_ulonglong2(acc[i][2], acc[i][3]);
        }
    }
    __syncthreads();
    if (q == 0) {
        float* dst = g_part + t * 4096;
#pragma unroll
        for (int i = 0; i < 8; ++i) {
#pragma unroll
            for (int qq = 0; qq < 3; ++qq) {
                const float* src = smA + qq * 4096;
                const ulonglong2 v0 = *(const ulonglong2*)&src[(d0 + i) * 64 + e0];
                const ulonglong2 v1 = *(const ulonglong2*)&src[(d0 + i) * 64 + e0 + 4];
                a2(acc[i][0], v0.x); a2(acc[i][1], v0.y);
                a2(acc[i][2], v1.x); a2(acc[i][3], v1.y);
            }
            *(ulonglong2*)&dst[(d0 + i) * 64 + e0]     = make_ulonglong2(acc[i][0], acc[i][1]);
            *(ulonglong2*)&dst[(d0 + i) * 64 + e0 + 4] = make_ulonglong2(acc[i][2], acc[i][3]);
        }
    }
}

// ---------------- kB1/kB2: deterministic reduction to S ----------------
__global__ void __launch_bounds__(256) kB1() {
    const int blk = blockIdx.x;
    const int tid = threadIdx.x;
    const float* src = g_part + (long)blk * 16 * 4096;
#pragma unroll
    for (int i = 0; i < 16; ++i) {
        const int x = tid + i * 256;
        float s = 0.0f;
#pragma unroll
        for (int tt = 0; tt < 16; ++tt) s += src[tt * 4096 + x];
        g_red[blk * 4096 + x] = s;
    }
}
__global__ void __launch_bounds__(256) kB2() {
    const int idx = blockIdx.x * 256 + threadIdx.x;   // idx = e*64+d
    const int d = idx & 63, e = idx >> 6;
    float s = 0.0f;
#pragma unroll 8
    for (int b = 0; b < B1_BLOCKS; ++b) s += g_red[b * 4096 + idx];
    g_S[d * 64 + e] = s;
}

// ---------------- kQO: out_t = (Q_t @ M_t) @ S ----------------
// grid 2048, block 128, smem 48 KB (4 CTAs/SM -> 16 warps).
// sQ XOR-swizzled (also holds P swizzled). sMS holds M, then S.
__global__ void __launch_bounds__(128, 4) kQO(const float* __restrict__ Qg,
                                              float* __restrict__ outg) {
    extern __shared__ float smQ[];
    float* sQ  = smQ;           // 128*64 swizzled
    float* sMS = smQ + 8192;    // 64*64: M, then S

    const int tid = threadIdx.x;
    const long t = blockIdx.x;

    const float4* M4 = (const float4*)g_part + t * 1024;
#pragma unroll
    for (int i = tid; i < 1024; i += 128)
        ((float4*)sMS)[i] = M4[i];

    const float4* Q4 = (const float4*)Qg + t * 2048;
#pragma unroll
    for (int i = tid; i < 2048; i += 128) {
        const float4 v = Q4[i];
        const int row = i >> 4;
        const int col = (i & 15) << 2;
        const int sw = ((row >> 3) & 7) << 2;
        *(float4*)&sQ[row * 64 + (col ^ sw)] = v;   // (col+j)^sw == (col^sw)+j
    }
    __syncthreads();

    const int r0 = (tid >> 3) * 8;   // 16 groups * 8 = 128 rows
    const int c0 = (tid & 7) * 8;    // 8 groups * 8 = 64 cols
    const int sw = ((r0 >> 3) & 7) << 2;

    unsigned long long acc[8][4];
#pragma unroll
    for (int i = 0; i < 8; ++i)
#pragma unroll
        for (int j = 0; j < 4; ++j) acc[i][j] = 0ull;

    // ---- GEMM1: P = Q_t @ M_t (A via float4 k-chunks) ----
#pragma unroll 2
    for (int k0 = 0; k0 < 64; k0 += 4) {
        float a[8][4];
#pragma unroll
        for (int i = 0; i < 8; ++i)
            *(float4*)a[i] = *(const float4*)&sQ[(r0 + i) * 64 + (k0 ^ sw)];
#pragma unroll
        for (int j = 0; j < 4; ++j) {
            const ulonglong2 b01 = *(const ulonglong2*)&sMS[(k0 + j) * 64 + c0];
            const ulonglong2 b23 = *(const ulonglong2*)&sMS[(k0 + j) * 64 + c0 + 4];
            const unsigned long long pb[4] = {b01.x, b01.y, b23.x, b23.y};
#pragma unroll
            for (int i = 0; i < 8; ++i) {
                const unsigned long long pa = bcast2(a[i][j]);
                f2(acc[i][0], pa, pb[0]); f2(acc[i][1], pa, pb[1]);
                f2(acc[i][2], pa, pb[2]); f2(acc[i][3], pa, pb[3]);
            }
        }
    }

    // prefetch S while GEMM1 drains (writes gated by the sync below)
    float4 sreg[8];
#pragma unroll
    for (int j = 0; j < 8; ++j)
        sreg[j] = ((const float4*)g_S)[tid + j * 128];

    __syncthreads();   // all sQ/sMS reads complete

    // store P swizzled into sQ; store S into sMS
#pragma unroll
    for (int i = 0; i < 8; ++i) {
        float4 p0, p1;
        *(ulonglong2*)&p0 = make_ulonglong2(acc[i][0], acc[i][1]);
        *(ulonglong2*)&p1 = make_ulonglong2(acc[i][2], acc[i][3]);
        const int row = r0 + i;
        *(float4*)&sQ[row * 64 + (c0 ^ sw)]       = p0;
        *(float4*)&sQ[row * 64 + ((c0 + 4) ^ sw)] = p1;
    }
#pragma unroll
    for (int j = 0; j < 8; ++j)
        ((float4*)sMS)[tid + j * 128] = sreg[j];
    __syncthreads();

    // ---- GEMM2: out = P @ S ----
#pragma unroll
    for (int i = 0; i < 8; ++i)
#pragma unroll
        for (int j = 0; j < 4; ++j) acc[i][j] = 0ull;

#pragma unroll 2
    for (int k0 = 0; k0 < 64; k0 += 4) {
        float a[8][4];
#pragma unroll
        for (int i = 0; i < 8; ++i)
            *(float4*)a[i] = *(const float4*)&sQ[(r0 + i) * 64 + (k0 ^ sw)];
#pragma unroll
        for (int j = 0; j < 4; ++j) {
            const ulonglong2 b01 = *(const ulonglong2*)&sMS[(k0 + j) * 64 + c0];
            const ulonglong2 b23 = *(const ulonglong2*)&sMS[(k0 + j) * 64 + c0 + 4];
            const unsigned long long pb[4] = {b01.x, b01.y, b23.x, b23.y};
#pragma unroll
            for (int i = 0; i < 8; ++i) {
                const unsigned long long pa = bcast2(a[i][j]);
                f2(acc[i][0], pa, pb[0]); f2(acc[i][1], pa, pb[1]);
                f2(acc[i][2], pa, pb[2]); f2(acc[i][3], pa, pb[3]);
            }
        }
    }

    float* outp = outg + t * (TRUNK * D);
#pragma unroll
    for (int i = 0; i < 8; ++i) {
        *(ulonglong2*)&outp[(r0 + i) * 64 + c0]     = make_ulonglong2(acc[i][0], acc[i][1]);
        *(ulonglong2*)&outp[(r0 + i) * 64 + c0 + 4] = make_ulonglong2(acc[i][2], acc[i][3]);
    }
}

#define SMEM_A_BYTES (2 * 128 * 64 * 4)          // 65536
#define SMEM_QO_BYTES ((8192 + 4096) * 4)        // 49152

extern "C" void kernel_launch(void* const* d_in, const int* in_sizes, int n_in,
                              void* d_out, int out_size) {
    const float* Q = (const float*)d_in[0];
    const float* K = (const float*)d_in[1];
    const float* V = (const float*)d_in[2];
    float* out = (float*)d_out;

    cudaFuncSetAttribute(kA, cudaFuncAttributeMaxDynamicSharedMemorySize, SMEM_A_BYTES);
    cudaFuncSetAttribute(kQO, cudaFuncAttributeMaxDynamicSharedMemorySize, SMEM_QO_BYTES);

    kA<<<T_TRUNKS, 256, SMEM_A_BYTES>>>(K, V);
    kB1<<<B1_BLOCKS, 256>>>();
    kB2<<<16, 256>>>();
    kQO<<<T_TRUNKS, 128, SMEM_QO_BYTES>>>(Q, out);
}